// round 17
// baseline (speedup 1.0000x reference)
#include <cuda_runtime.h>
#include <cuda_bf16.h>
#include <cstdint>

typedef unsigned long long u64;
typedef long long i64;
typedef uint32_t u32;

#define EPS 1e-5f
#define VEC 8704
#define OF_AH VEC                    // A hi plane: 64 tiles x 512B = 32768
#define OF_AL (OF_AH + 32768)
#define OF_WH (OF_AL + 32768)        // W hi half:  64 tiles x 256B = 16384
#define OF_WL (OF_WH + 16384)
#define SMEMB (OF_WL + 16384)        // 107008 -> 2 CTAs/SM

#define NBMAX 800

// ---------------- scratch (device globals; no runtime alloc) ----------------
__device__ __align__(16) u32 XPHU[NBMAX * 8192];    // actors hi plane, fragment-major
__device__ __align__(16) u32 XPLU[NBMAX * 8192];    // actors lo plane
__device__ __align__(16) u32 WSPU[17 * 16384];      // W: [id][plane][half][n8][ksh][lane][j]
__device__ __align__(16) u32 WOSPU[6 * 16384];      // Wo images, same layout
__device__ __align__(16) float S3[600000u * 60];    // preds
__device__ __align__(16) float S4[600000];          // cls logits
__device__ __align__(16) float S5[100000u * 128];   // actB fp32

// ---------------- helpers ----------------------------------------------------
__device__ __forceinline__ u32 packbf(float x) {
    u32 hb = (u32)__bfloat16_as_ushort(__float2bfloat16(x));
    float r = x - __uint_as_float(hb << 16);
    return (hb << 16) | (u32)__bfloat16_as_ushort(__float2bfloat16(r));
}
__device__ __forceinline__ void mma16816(float* c, const u32* a, const u32* b) {
    asm volatile(
        "mma.sync.aligned.m16n8k16.row.col.f32.bf16.bf16.f32 "
        "{%0,%1,%2,%3}, {%4,%5,%6,%7}, {%8,%9}, {%0,%1,%2,%3};"
        : "+f"(c[0]), "+f"(c[1]), "+f"(c[2]), "+f"(c[3])
        : "r"(a[0]), "r"(a[1]), "r"(a[2]), "r"(a[3]), "r"(b[0]), "r"(b[1]));
}
__device__ __forceinline__ u32 smem_u32p(const void* p) {
    u32 a;
    asm("{ .reg .u64 t; cvta.to.shared.u64 t, %1; cvt.u32.u64 %0, t; }" : "=r"(a) : "l"(p));
    return a;
}
__device__ __forceinline__ void cpa16(u32 dst, const void* src, int sz) {
    asm volatile("cp.async.ca.shared.global [%0], [%1], 16, %2;"
                 :: "r"(dst), "l"(src), "r"(sz) : "memory");
}
#define CPA_COMMIT() asm volatile("cp.async.commit_group;" ::: "memory")
#define CPA_WAIT0()  asm volatile("cp.async.wait_group 0;" ::: "memory")

// ---------------- prep kernels (fragment-major global images) ----------------
// W image per plane (8192 u32): off = half*4096 + (n8*4+ksh)*64 + lane*2 + j
__global__ void prep_w(const float* pW1, const float* pW2, const float* dW1,
                       const float* aW, const float* cW1, const float* cW2)
{
    int id = blockIdx.x;
    const float* W;
    if      (id < 6)   W = pW1 + id * 16384;
    else if (id < 12)  W = pW2 + (id - 6) * 16384;
    else if (id == 12) W = dW1;
    else if (id == 13) W = aW;
    else if (id == 14) W = aW + 16384;
    else if (id == 15) W = cW1;
    else               W = cW2;
    for (int idx = threadIdx.x; idx < 8192; idx += blockDim.x) {
        int n = idx >> 6, p = idx & 63;                  // B row n, k-pair p
        float x0 = W[(2 * p) * 128 + n];                 // B[n][k] = W[k][n]
        float x1 = W[(2 * p + 1) * 128 + n];
        u32 p0 = packbf(x0), p1 = packbf(x1);
        int n8 = n >> 3, gg = n & 7;
        int ks = p >> 3, pin = p & 7, j = pin >> 2, tg = pin & 3;
        u32 off = (u32)(ks >> 2) * 4096 + ((n8 * 4 + (ks & 3)) * 64) + (gg * 4 + tg) * 2 + j;
        WSPU[id * 16384u + off]        = (p0 >> 16) | (p1 & 0xffff0000u);
        WSPU[id * 16384u + 8192 + off] = (p0 & 0xffffu) | (p1 << 16);
    }
}
__global__ void prep_wo(const float* pWo) {
    int y = blockIdx.x;
    for (int idx = threadIdx.x; idx < 8192; idx += blockDim.x) {
        int o = idx >> 6, p = idx & 63;
        float x0 = (o < 60) ? pWo[y * 7680 + (2 * p) * 60 + o] : 0.f;
        float x1 = (o < 60) ? pWo[y * 7680 + (2 * p + 1) * 60 + o] : 0.f;
        u32 p0 = packbf(x0), p1 = packbf(x1);
        int n8 = o >> 3, gg = o & 7;
        int ks = p >> 3, pin = p & 7, j = pin >> 2, tg = pin & 3;
        u32 off = (u32)(ks >> 2) * 4096 + ((n8 * 4 + (ks & 3)) * 64) + (gg * 4 + tg) * 2 + j;
        WOSPU[y * 16384u + off]        = (p0 >> 16) | (p1 & 0xffff0000u);
        WOSPU[y * 16384u + 8192 + off] = (p0 & 0xffffu) | (p1 << 16);
    }
}
// A image per 128-row block (8192 u32/plane): tile(r16,ks)*128 + slot(lane)*4 + h + 2*kj
__global__ void prep_x(const float* a, int N, int NB) {
    int idx = blockIdx.x * blockDim.x + threadIdx.x;
    if (idx >= NB * 8192) return;
    int r = idx >> 6, p = idx & 63;
    float x0 = 0.f, x1 = 0.f;
    if (r < N) { x0 = a[(size_t)r * 128 + 2 * p]; x1 = a[(size_t)r * 128 + 2 * p + 1]; }
    u32 p0 = packbf(x0), p1 = packbf(x1);
    int blk = r >> 7, ri = r & 127;
    int r16 = ri >> 4, rq = ri & 15, h = rq >> 3, gg = rq & 7;
    int ks = p >> 3, pin = p & 7, kj = pin >> 2, tg = pin & 3;
    int lane = gg * 4 + tg; lane ^= (lane >> 3);
    u32 off = (u32)blk * 8192 + (r16 * 8 + ks) * 128 + lane * 4 + h + 2 * kj;
    XPHU[off] = (p0 >> 16) | (p1 & 0xffff0000u);
    XPLU[off] = (p0 & 0xffffu) | (p1 << 16);
}

// ---------------- staging (verbatim cp.async copies) --------------------------
__device__ __forceinline__ void stageA_cpa(u32 sb, int tid, int blk) {
    const u32* sH = XPHU + (size_t)blk * 8192;
    const u32* sL = XPLU + (size_t)blk * 8192;
    #pragma unroll
    for (int i = 0; i < 8; i++) {
        int idx = tid + 256 * i;                       // 2048 chunks / plane
        cpa16(sb + OF_AH + idx * 16, sH + idx * 4, 16);
        cpa16(sb + OF_AL + idx * 16, sL + idx * 4, 16);
    }
}
__device__ __forceinline__ void stageW_cpa(const u32* Wp, int half, u32 sb, int tid) {
    const u32* h0 = Wp + half * 4096;
    #pragma unroll
    for (int i = 0; i < 4; i++) {
        int idx = tid + 256 * i;                       // 1024 chunks / plane
        cpa16(sb + OF_WH + idx * 16, h0 + idx * 4, 16);
        cpa16(sb + OF_WL + idx * 16, h0 + 8192 + idx * 4, 16);
    }
}

// ---------------- MMA over one W k-half (term-major issue order) --------------
// Dependent MMAs on the same accumulator are separated by >=8 independent
// MMAs (term-major sweep over an mt-pair x 4 nt), hiding HMMA latency.
// Per-accumulator term order is unchanged (hh, lh, hl per k-chunk).
template <int MT>
__device__ __forceinline__ void mma_half(const char* smc, int rbase, int nbase,
                                         int lane, int ks0, float (&acc)[MT][4][4])
{
    const char* Ahi = smc + OF_AH; const char* Alo = smc + OF_AL;
    const char* Wh  = smc + OF_WH; const char* Wl  = smc + OF_WL;
    const int sl = (lane ^ (lane >> 3)) * 16;
    const int wl = lane * 8;
    #pragma unroll
    for (int kh = 0; kh < 4; kh++) {
        u32 bh[4][2], bl[4][2];
        #pragma unroll
        for (int nt = 0; nt < 4; nt++) {
            int off = (((nbase >> 3) + nt) * 4 + kh) * 256 + wl;
            uint2 t = *(const uint2*)(Wh + off); bh[nt][0] = t.x; bh[nt][1] = t.y;
            uint2 u = *(const uint2*)(Wl + off); bl[nt][0] = u.x; bl[nt][1] = u.y;
        }
        #pragma unroll
        for (int mg = 0; mg < (MT + 1) / 2; mg++) {
            const int m0 = mg * 2;
            const int nm = (MT - m0 < 2) ? 1 : 2;
            u32 ah[2][4], al[2][4];
            #pragma unroll
            for (int mi = 0; mi < 2; mi++) {
                if (mi < nm) {
                    int aoff = ((((rbase >> 4) + m0 + mi) * 8) + ks0 + kh) * 512 + sl;
                    uint4 qh = *(const uint4*)(Ahi + aoff);
                    uint4 ql = *(const uint4*)(Alo + aoff);
                    ah[mi][0] = qh.x; ah[mi][1] = qh.y; ah[mi][2] = qh.z; ah[mi][3] = qh.w;
                    al[mi][0] = ql.x; al[mi][1] = ql.y; al[mi][2] = ql.z; al[mi][3] = ql.w;
                }
            }
            // term-major: 8 independent MMAs between revisits of any acc
            #pragma unroll
            for (int mi = 0; mi < 2; mi++)
                if (mi < nm) {
                    #pragma unroll
                    for (int nt = 0; nt < 4; nt++) mma16816(acc[m0 + mi][nt], ah[mi], bh[nt]);
                }
            #pragma unroll
            for (int mi = 0; mi < 2; mi++)
                if (mi < nm) {
                    #pragma unroll
                    for (int nt = 0; nt < 4; nt++) mma16816(acc[m0 + mi][nt], al[mi], bh[nt]);
                }
            #pragma unroll
            for (int mi = 0; mi < 2; mi++)
                if (mi < nm) {
                    #pragma unroll
                    for (int nt = 0; nt < 4; nt++) mma16816(acc[m0 + mi][nt], ah[mi], bl[nt]);
                }
        }
    }
}

// ---------------- accumulator epilogue (GN/res/relu/dot/writes) ---------------
// Prefetches nextW half-0 under the epilogue (legal only when gb4 != null).
__device__ __forceinline__ void epi_main(
    char* smc, u32 sb, float (&acc)[4][4][4],
    int tid, int wm, int wn, int g, int tg, int row0, int M,
    const float4* gb4, const float* pre, const float* post, int relu,
    const float2* wv2, const float* wob, float* dot,
    float* outF, int writeA, const u32* nextW)
{
    float2* sred = (float2*)(smc + 4608);
    const int lane = tid & 31;
    const int cbase = wn * 32 + tg * 2;
    const int rloc0 = wm * 64 + g;

    if (pre) {
        #pragma unroll
        for (int mt = 0; mt < 4; mt++)
        #pragma unroll
        for (int h = 0; h < 2; h++) {
            int R = row0 + rloc0 + mt * 16 + 8 * h;
            if (R < M) {
                const float* pr = pre + (size_t)(R / 6) * 128;
                #pragma unroll
                for (int nt = 0; nt < 4; nt++) {
                    float2 a = *(const float2*)(pr + cbase + nt * 8);
                    acc[mt][nt][2*h] += a.x; acc[mt][nt][2*h+1] += a.y;
                }
            }
        }
    }
    if (gb4) {
        #pragma unroll
        for (int mt = 0; mt < 4; mt++)
        #pragma unroll
        for (int h = 0; h < 2; h++) {
            float s = 0.f, ss = 0.f;
            #pragma unroll
            for (int nt = 0; nt < 4; nt++) {
                float x = acc[mt][nt][2*h], yv = acc[mt][nt][2*h+1];
                s += x + yv; ss += x * x + yv * yv;
            }
            s += __shfl_xor_sync(~0u, s, 1); ss += __shfl_xor_sync(~0u, ss, 1);
            s += __shfl_xor_sync(~0u, s, 2); ss += __shfl_xor_sync(~0u, ss, 2);
            if (tg == 0) sred[(rloc0 + mt * 16 + 8 * h) * 4 + wn] = make_float2(s, ss);
        }
        __syncthreads();
        if (nextW) { stageW_cpa(nextW, 0, sb, tid); CPA_COMMIT(); }
        float mv[4][2], iv[4][2];
        #pragma unroll
        for (int mt = 0; mt < 4; mt++)
        #pragma unroll
        for (int h = 0; h < 2; h++) {
            int rl = (rloc0 + mt * 16 + 8 * h) * 4;
            float2 t0 = sred[rl], t1 = sred[rl+1], t2 = sred[rl+2], t3 = sred[rl+3];
            float s = t0.x + t1.x + t2.x + t3.x, ss = t0.y + t1.y + t2.y + t3.y;
            float m = s * (1.f / 128.f);
            mv[mt][h] = m;
            iv[mt][h] = rsqrtf(ss * (1.f / 128.f) - m * m + EPS);
        }
        #pragma unroll
        for (int nt = 0; nt < 4; nt++) {
            float4 q = gb4[(cbase + nt * 8) >> 1];
            #pragma unroll
            for (int mt = 0; mt < 4; mt++)
            #pragma unroll
            for (int h = 0; h < 2; h++) {
                acc[mt][nt][2*h]   = (acc[mt][nt][2*h]   - mv[mt][h]) * iv[mt][h] * q.x + q.y;
                acc[mt][nt][2*h+1] = (acc[mt][nt][2*h+1] - mv[mt][h]) * iv[mt][h] * q.z + q.w;
            }
        }
    }
    if (post) {
        #pragma unroll
        for (int mt = 0; mt < 4; mt++)
        #pragma unroll
        for (int h = 0; h < 2; h++) {
            int R = row0 + rloc0 + mt * 16 + 8 * h;
            if (R < M) {
                const float* pr = post + (size_t)R * 128;
                #pragma unroll
                for (int nt = 0; nt < 4; nt++) {
                    float2 a = *(const float2*)(pr + cbase + nt * 8);
                    acc[mt][nt][2*h] += a.x; acc[mt][nt][2*h+1] += a.y;
                }
            }
        }
    }
    if (relu) {
        #pragma unroll
        for (int mt = 0; mt < 4; mt++)
        #pragma unroll
        for (int nt = 0; nt < 4; nt++)
        #pragma unroll
        for (int q = 0; q < 4; q++) acc[mt][nt][q] = fmaxf(acc[mt][nt][q], 0.f);
    }
    if (wv2) {
        __syncthreads();
        #pragma unroll
        for (int mt = 0; mt < 4; mt++)
        #pragma unroll
        for (int h = 0; h < 2; h++) {
            float d = 0.f;
            #pragma unroll
            for (int nt = 0; nt < 4; nt++) {
                float2 w = wv2[(cbase + nt * 8) >> 1];
                d += acc[mt][nt][2*h] * w.x + acc[mt][nt][2*h+1] * w.y;
            }
            d += __shfl_xor_sync(~0u, d, 1);
            d += __shfl_xor_sync(~0u, d, 2);
            if (tg == 0) sred[(rloc0 + mt * 16 + 8 * h) * 4 + wn].x = d;
        }
        __syncthreads();
        if (wn == 0 && tg == 0) {
            #pragma unroll
            for (int mt = 0; mt < 4; mt++)
            #pragma unroll
            for (int h = 0; h < 2; h++) {
                int rl = (rloc0 + mt * 16 + 8 * h) * 4;
                float t = sred[rl].x + sred[rl+1].x + sred[rl+2].x + sred[rl+3].x;
                int R = row0 + rloc0 + mt * 16 + 8 * h;
                if (R < M) dot[R] = t + wob[0];
            }
        }
    }
    if (outF) {
        #pragma unroll
        for (int mt = 0; mt < 4; mt++)
        #pragma unroll
        for (int h = 0; h < 2; h++) {
            int R = row0 + rloc0 + mt * 16 + 8 * h;
            if (R < M) {
                float* o = outF + (size_t)R * 128;
                #pragma unroll
                for (int nt = 0; nt < 4; nt++)
                    *(float2*)(o + cbase + nt * 8) = make_float2(acc[mt][nt][2*h], acc[mt][nt][2*h+1]);
            }
        }
    }
    if (writeA) {
        char* Ahi = smc + OF_AH; char* Alo = smc + OF_AL;
        const int sl = (lane ^ (lane >> 3)) * 16;
        #pragma unroll
        for (int mt = 0; mt < 4; mt++)
        #pragma unroll
        for (int nt = 0; nt < 4; nt++) {
            int tile = (wm * 4 + mt) * 8 + wn * 2 + (nt >> 1);
            int off = tile * 512 + sl + (nt & 1) * 8;
            u32 p00 = packbf(acc[mt][nt][0]), p01 = packbf(acc[mt][nt][1]);
            u32 p10 = packbf(acc[mt][nt][2]), p11 = packbf(acc[mt][nt][3]);
            *(uint2*)(Ahi + off) = make_uint2((p00 >> 16) | (p01 & 0xffff0000u),
                                             (p10 >> 16) | (p11 & 0xffff0000u));
            *(uint2*)(Alo + off) = make_uint2((p00 & 0xffffu) | (p01 << 16),
                                             (p10 & 0xffffu) | (p11 << 16));
        }
    }
}

// ---------------- one fused 128x128 stage ------------------------------------
// Entry contract: this stage's W half-0 cp.async is committed.
__device__ __forceinline__ void stage128(
    char* smc, u32 sb, const u32* Wsrc, const u32* nextW,
    int tid, int row0, int M,
    const float4* gb4, const float* pre, const float* post, int relu,
    const float2* wv2, const float* wob, float* dot, float* outF, int writeA)
{
    const int wid = tid >> 5, lane = tid & 31;
    const int wm = wid >> 2, wn = wid & 3, g = lane >> 2, tg = lane & 3;
    float acc[4][4][4];
    #pragma unroll
    for (int i = 0; i < 4; i++)
        #pragma unroll
        for (int j = 0; j < 4; j++)
            #pragma unroll
            for (int q = 0; q < 4; q++) acc[i][j][q] = 0.f;

    CPA_WAIT0();
    __syncthreads();
    mma_half<4>(smc, wm * 64, wn * 32, lane, 0, acc);
    __syncthreads();
    stageW_cpa(Wsrc, 1, sb, tid); CPA_COMMIT(); CPA_WAIT0();
    __syncthreads();
    mma_half<4>(smc, wm * 64, wn * 32, lane, 4, acc);
    epi_main(smc, sb, acc, tid, wm, wn, g, tg, row0, M, gb4, pre, post, relu,
             wv2, wob, dot, outF, writeA, nextW);
    __syncthreads();
}

// ---------------- K1: fused pred head ----------------------------------------
__global__ void __launch_bounds__(256, 2) k_pred(
    const float* actors, const float* pg1, const float* pb1,
    const float* pg2, const float* pb2, const float* pbo, int N)
{
    extern __shared__ char smc[];
    float4* gb0 = (float4*)smc;
    float4* gb1 = (float4*)(smc + 1024);
    float2* bias2 = (float2*)(smc + 4096);
    const u32 sb = smem_u32p(smc);
    const int tid = threadIdx.x;
    const int y = blockIdx.y, row0 = blockIdx.x * 128;

    stageA_cpa(sb, tid, blockIdx.x);
    stageW_cpa(WSPU + y * 16384, 0, sb, tid);
    CPA_COMMIT();

    if (tid < 64) {
        int c = 2 * tid;
        gb0[tid] = make_float4(pg1[y*128+c], pb1[y*128+c], pg1[y*128+c+1], pb1[y*128+c+1]);
        gb1[tid] = make_float4(pg2[y*128+c], pb2[y*128+c], pg2[y*128+c+1], pb2[y*128+c+1]);
    }
    if (tid < 32) {
        int c = 2 * tid;
        bias2[tid] = make_float2(c < 60 ? pbo[y*60+c] : 0.f, c+1 < 60 ? pbo[y*60+c+1] : 0.f);
    }

    stage128(smc, sb, WSPU + y * 16384, WSPU + (6 + y) * 16384, tid, row0, N,
             gb0, nullptr, nullptr, 1, nullptr, nullptr, nullptr, nullptr, 1);
    stage128(smc, sb, WSPU + (6 + y) * 16384, WOSPU + y * 16384, tid, row0, N,
             gb1, nullptr, actors, 1, nullptr, nullptr, nullptr, nullptr, 1);

    // stage 2: preds = h @ Wo + bias (64-wide, cols 0..59 valid)
    {
        const int wid = tid >> 5, lane = tid & 31;
        const int g = lane >> 2, tg = lane & 3;
        const int rbase = (wid >> 1) * 32, nbase = (wid & 1) * 32;
        float acc[2][4][4];
        #pragma unroll
        for (int i = 0; i < 2; i++)
            #pragma unroll
            for (int j = 0; j < 4; j++)
                #pragma unroll
                for (int q = 0; q < 4; q++) acc[i][j][q] = 0.f;
        CPA_WAIT0();
        __syncthreads();
        mma_half<2>(smc, rbase, nbase, lane, 0, acc);
        __syncthreads();
        stageW_cpa(WOSPU + y * 16384, 1, sb, tid); CPA_COMMIT(); CPA_WAIT0();
        __syncthreads();
        mma_half<2>(smc, rbase, nbase, lane, 4, acc);
        #pragma unroll
        for (int mt = 0; mt < 2; mt++)
        #pragma unroll
        for (int h = 0; h < 2; h++) {
            int R = row0 + rbase + mt * 16 + g + 8 * h;
            if (R < N) {
                float* o = S3 + (size_t)R * 360 + y * 60;
                #pragma unroll
                for (int nt = 0; nt < 4; nt++) {
                    int c = nbase + nt * 8 + tg * 2;
                    if (c < 60) {
                        float2 bb = bias2[c >> 1];
                        o[c]     = acc[mt][nt][2*h]   + bb.x;
                        o[c + 1] = acc[mt][nt][2*h+1] + bb.y;
                    }
                }
            }
        }
    }
}

// ---------------- K2: actB = actors @ agt_W[128:256] -------------------------
__global__ void __launch_bounds__(256, 2) k_actB(int N)
{
    extern __shared__ char smc[];
    const u32 sb = smem_u32p(smc);
    const int tid = threadIdx.x;
    const int row0 = blockIdx.x * 128;

    stageA_cpa(sb, tid, blockIdx.x);
    stageW_cpa(WSPU + 14 * 16384, 0, sb, tid);
    CPA_COMMIT();

    stage128(smc, sb, WSPU + 14 * 16384, nullptr, tid, row0, N,
             nullptr, nullptr, nullptr, 0, nullptr, nullptr, nullptr, S5, 0);
}

// ---------------- K3: fused chain (dist -> agt -> cls1 -> cls2) --------------
__global__ void __launch_bounds__(256, 2) k_chain(
    const float* dW0, const float* db0, const float* dg1, const float* db1v,
    const float* ag, const float* ab, const float* cg1, const float* cb1,
    const float* cg2, const float* cb2, const float* cWo, const float* cbo,
    float* feats, int M)
{
    extern __shared__ char smc[];
    float4* gbA = (float4*)smc;
    float4* gbB = (float4*)(smc + 1024);
    float4* gbC = (float4*)(smc + 2048);
    float4* gbD = (float4*)(smc + 3072);
    float2* wv2 = (float2*)(smc + 4096);
    float* w0a = (float*)(smc + 4608);
    float* w0b = (float*)(smc + 5120);
    float* b0v = (float*)(smc + 5632);
    float* pav = (float*)(smc + 6144);
    float* pbv = (float*)(smc + 6656);
    u32* Ahi = (u32*)(smc + OF_AH); u32* Alo = (u32*)(smc + OF_AL);
    const u32 sb = smem_u32p(smc);

    const int tid = threadIdx.x;
    const int row0 = blockIdx.x * 128;

    stageW_cpa(WSPU + 12 * 16384, 0, sb, tid);
    CPA_COMMIT();

    if (tid < 64) {
        int c = 2 * tid;
        gbA[tid] = make_float4(dg1[c], db1v[c], dg1[c+1], db1v[c+1]);
        gbB[tid] = make_float4(ag[c],  ab[c],   ag[c+1],  ab[c+1]);
        gbC[tid] = make_float4(cg1[c], cb1[c],  cg1[c+1], cb1[c+1]);
        gbD[tid] = make_float4(cg2[c], cb2[c],  cg2[c+1], cb2[c+1]);
        wv2[tid] = make_float2(cWo[c], cWo[c+1]);
    }
    if (tid < 128) {
        w0a[tid] = dW0[tid]; w0b[tid] = dW0[128 + tid]; b0v[tid] = db0[tid];
        int R = row0 + tid; float a = 0.f, bq = 0.f;
        if (R < M) { a = S3[(size_t)R * 60 + 58]; bq = S3[(size_t)R * 60 + 59]; }
        pav[tid] = a; pbv[tid] = bq;
    }
    __syncthreads();

    // generate dist A in fragment layout: relu(b0 - p58*W0[0] - p59*W0[1])
    #pragma unroll
    for (int it = 0; it < 32; it++) {
        int idx = tid + it * 256;                 // 8192 = 128 rows x 64 pairs
        int r = idx >> 6, p = idx & 63;
        int k2 = 2 * p;
        float x0 = fmaxf(b0v[k2]     - pav[r] * w0a[k2]     - pbv[r] * w0b[k2],     0.f);
        float x1 = fmaxf(b0v[k2 + 1] - pav[r] * w0a[k2 + 1] - pbv[r] * w0b[k2 + 1], 0.f);
        u32 p0 = packbf(x0), p1 = packbf(x1);
        int r16 = r >> 4, rq = r & 15, h = rq >> 3, gg = rq & 7;
        int ks = p >> 3, pin = p & 7, kj = pin >> 2, tg = pin & 3;
        int lane = gg * 4 + tg; lane ^= (lane >> 3);
        u32 off = (u32)(r16 * 8 + ks) * 128 + lane * 4 + h + 2 * kj;
        Ahi[off] = (p0 >> 16) | (p1 & 0xffff0000u);
        Alo[off] = (p0 & 0xffffu) | (p1 << 16);
    }

    stage128(smc, sb, WSPU + 12 * 16384, WSPU + 13 * 16384, tid, row0, M,
             gbA, nullptr, nullptr, 1, nullptr, nullptr, nullptr, nullptr, 1);
    stage128(smc, sb, WSPU + 13 * 16384, WSPU + 15 * 16384, tid, row0, M,
             gbB, S5, nullptr, 1, nullptr, nullptr, nullptr, feats, 1);
    stage128(smc, sb, WSPU + 15 * 16384, WSPU + 16 * 16384, tid, row0, M,
             gbC, nullptr, nullptr, 1, nullptr, nullptr, nullptr, nullptr, 1);
    stage128(smc, sb, WSPU + 16 * 16384, nullptr, tid, row0, M,
             gbD, nullptr, feats, 1, wv2, cbo, S4, nullptr, 0);
}

// ---------------- softmax + rank-sort + reg gather ---------------------------
__global__ void finalize(const float* ctr, float* clsO, float* regO, int N)
{
    int w = (blockIdx.x * blockDim.x + threadIdx.x) >> 5;
    int lane = threadIdx.x & 31;
    if (w >= N) return;
    float v = (lane < 6) ? S4[(size_t)w * 6 + lane] : -3.4e38f;
    float m = v;
    #pragma unroll
    for (int s = 4; s >= 1; s >>= 1) m = fmaxf(m, __shfl_xor_sync(~0u, m, s));
    float e = (lane < 6) ? expf(v - m) : 0.f;
    float s = e;
    #pragma unroll
    for (int t = 4; t >= 1; t >>= 1) s += __shfl_xor_sync(~0u, s, t);
    float pr = e / s;
    int rk = 0;
    #pragma unroll
    for (int j = 0; j < 6; j++) {
        float pj = __shfl_sync(~0u, pr, j);
        rk += (pj > pr) || (pj == pr && j < lane);
    }
    if (lane < 6) clsO[(size_t)w * 6 + rk] = pr;
    float cx = ctr[(size_t)w * 2], cy = ctr[(size_t)w * 2 + 1];
    for (int k = 0; k < 6; k++) {
        int r = __shfl_sync(~0u, rk, k);
        const float* sp = S3 + (size_t)w * 360 + k * 60;
        float* dp = regO + ((size_t)w * 6 + r) * 60;
        for (int j = lane; j < 60; j += 32) dp[j] = sp[j] + ((j & 1) ? cy : cx);
    }
}

// ---------------- host orchestration ----------------------------------------
extern "C" void kernel_launch(void* const* d_in, const int* in_sizes, int n_in,
                              void* d_out, int out_size)
{
    const float* actors = (const float*)d_in[0];
    const float* ctrs   = (const float*)d_in[1];
    const float* pW1 = (const float*)d_in[2];
    const float* pg1 = (const float*)d_in[3];
    const float* pb1 = (const float*)d_in[4];
    const float* pW2 = (const float*)d_in[5];
    const float* pg2 = (const float*)d_in[6];
    const float* pb2 = (const float*)d_in[7];
    const float* pWo = (const float*)d_in[8];
    const float* pbo = (const float*)d_in[9];
    const float* dW0 = (const float*)d_in[10];
    const float* db0 = (const float*)d_in[11];
    const float* dW1 = (const float*)d_in[12];
    const float* dg1 = (const float*)d_in[13];
    const float* db1 = (const float*)d_in[14];
    const float* aW  = (const float*)d_in[15];
    const float* ag  = (const float*)d_in[16];
    const float* ab  = (const float*)d_in[17];
    const float* cW1 = (const float*)d_in[18];
    const float* cg1 = (const float*)d_in[19];
    const float* cb1 = (const float*)d_in[20];
    const float* cW2 = (const float*)d_in[21];
    const float* cg2 = (const float*)d_in[22];
    const float* cb2 = (const float*)d_in[23];
    const float* cWo = (const float*)d_in[24];
    const float* cbo = (const float*)d_in[25];

    const int N = in_sizes[0] / 128;       // 100000
    const int M = N * 6;
    const int gN = (N + 127) / 128, gM = (M + 127) / 128;
    float* out   = (float*)d_out;
    float* regO  = out + (size_t)N * 6;
    float* feats = regO + (size_t)N * 360;

    cudaFuncSetAttribute(k_pred,  cudaFuncAttributeMaxDynamicSharedMemorySize, SMEMB);
    cudaFuncSetAttribute(k_actB,  cudaFuncAttributeMaxDynamicSharedMemorySize, SMEMB);
    cudaFuncSetAttribute(k_chain, cudaFuncAttributeMaxDynamicSharedMemorySize, SMEMB);

    prep_w<<<17, 256>>>(pW1, pW2, dW1, aW, cW1, cW2);
    prep_wo<<<6, 256>>>(pWo);
    prep_x<<<(gN * 8192 + 255) / 256, 256>>>(actors, N, gN);

    k_pred<<<dim3(gN, 6), 256, SMEMB>>>(actors, pg1, pb1, pg2, pb2, pbo, N);
    k_actB<<<gN, 256, SMEMB>>>(N);
    k_chain<<<gM, 256, SMEMB>>>(dW0, db0, dg1, db1, ag, ab, cg1, cb1,
                                cg2, cb2, cWo, cbo, feats, M);
    finalize<<<(N + 7) / 8, 256>>>(ctrs, out, regO, N);
}